// round 4
// baseline (speedup 1.0000x reference)
#include <cuda_runtime.h>
#include <math.h>

// Problem constants
#define BB 32
#define TT 1024
#define HH 1024
#define LL 4

// Recurrence kernel config
#define NCTA 128      // persistent CTAs (<= 148 SMs, 1 CTA/SM due to SMEM)
#define CPC  8        // h columns per CTA (128 * 8 = 1024)
#define RNN_SMEM ((CPC*HH + HH*BB + 256) * 4)   // Wh slice + h + reduce buf = 164,864 B

// -------------------- device scratch (no allocations allowed) --------------------
__device__ float g_S0[BB * TT * HH];   // 128 MB ping
__device__ float g_S1[BB * TT * HH];   // 128 MB pong
__device__ float g_hA[HH * BB];        // h ping  (transposed layout [k][b])
__device__ float g_hB[HH * BB];        // h pong
__device__ unsigned g_bar;             // grid barrier counter (reset by gemm block 0)

// Accurate tanh independent of -use_fast_math's tanhf->MUFU.TANH (2^-10.7 err).
// __expf (MUFU.EX2 based) is ~2 ulp; overall error ~1e-7 relative.
__device__ __forceinline__ float tanh_acc(float x)
{
    float ax = fabsf(x);
    float e  = __expf(-2.0f * ax);
    float r  = (1.0f - e) / (1.0f + e);
    return copysignf(r, x);
}

// -------------------- GEMM: C[M,1024] = A[M,1024] @ W[1024,1024] + bias --------------------
// 128x128 block tile, K-tile 8, 256 threads, 8x8 per-thread microtile.
// Also resets the grid-barrier counter (block 0) so the following persistent
// recurrence kernel starts from a clean barrier state (stream order => visible).
__global__ void __launch_bounds__(256, 2)
gemm_bias_kernel(const float* __restrict__ A, const float* __restrict__ W,
                 const float* __restrict__ bias, float* __restrict__ C)
{
    if (blockIdx.x == 0 && blockIdx.y == 0 && threadIdx.x == 0) g_bar = 0u;

    __shared__ float As[8][128];
    __shared__ float Bs[8][128];

    const int tid = threadIdx.x;
    const int tx = tid & 15;        // 16 col-threads
    const int ty = tid >> 4;        // 16 row-threads
    const int bm = blockIdx.y;      // 256 row tiles
    const int bn = blockIdx.x;      // 8 col tiles

    const float* Ab = A + bm * 128 * HH;
    const float* Wb = W + bn * 128;

    float acc[8][8];
#pragma unroll
    for (int i = 0; i < 8; i++)
#pragma unroll
        for (int j = 0; j < 8; j++) acc[i][j] = 0.0f;

    const int lrow = tid >> 1;          // 128 rows, 2 threads per row
    const int lseg = (tid & 1) * 4;     // k sub-segment
    const int bkr  = tid >> 5;          // 8 k-rows of B
    const int bcs  = (tid & 31) * 4;    // 128 cols / 32 lanes * float4

    // register prefetch of first tile
    float4 av = *(const float4*)(Ab + lrow * HH + lseg);
    float4 bv = *(const float4*)(Wb + bkr * HH + bcs);

    for (int k0 = 0; k0 < HH; k0 += 8) {
        // stage current tile to SMEM (A transposed)
        As[lseg + 0][lrow] = av.x;
        As[lseg + 1][lrow] = av.y;
        As[lseg + 2][lrow] = av.z;
        As[lseg + 3][lrow] = av.w;
        *(float4*)&Bs[bkr][bcs] = bv;
        __syncthreads();

        // prefetch next tile into registers (overlaps with compute below)
        if (k0 + 8 < HH) {
            av = *(const float4*)(Ab + lrow * HH + (k0 + 8) + lseg);
            bv = *(const float4*)(Wb + (k0 + 8 + bkr) * HH + bcs);
        }

#pragma unroll
        for (int kk = 0; kk < 8; kk++) {
            float a[8], b[8];
            *(float4*)&a[0] = *(const float4*)&As[kk][ty * 8];
            *(float4*)&a[4] = *(const float4*)&As[kk][ty * 8 + 4];
            *(float4*)&b[0] = *(const float4*)&Bs[kk][tx * 8];
            *(float4*)&b[4] = *(const float4*)&Bs[kk][tx * 8 + 4];
#pragma unroll
            for (int i = 0; i < 8; i++)
#pragma unroll
                for (int j = 0; j < 8; j++)
                    acc[i][j] = fmaf(a[i], b[j], acc[i][j]);
        }
        __syncthreads();
    }

    // epilogue: add bias, store
#pragma unroll
    for (int i = 0; i < 8; i++) {
        const int row = bm * 128 + ty * 8 + i;
#pragma unroll
        for (int j = 0; j < 8; j += 4) {
            const int col = bn * 128 + tx * 8 + j;
            float4 o;
            o.x = acc[i][j + 0] + bias[col + 0];
            o.y = acc[i][j + 1] + bias[col + 1];
            o.z = acc[i][j + 2] + bias[col + 2];
            o.w = acc[i][j + 3] + bias[col + 3];
            *(float4*)(C + row * HH + col) = o;
        }
    }
}

// -------------------- grid barrier (monotonic counter, reset per launch by gemm) -------------
__device__ __forceinline__ void grid_bar_sync(unsigned target)
{
    __syncthreads();
    if (threadIdx.x == 0) {
        __threadfence();                 // make this CTA's global writes visible (cumulative)
        atomicAdd(&g_bar, 1u);
        while (*((volatile unsigned*)&g_bar) < target) { __nanosleep(64); }
        __threadfence();                 // acquire side
    }
    __syncthreads();
}

// -------------------- Recurrence: one persistent kernel per layer --------------------
// CTA c owns h columns [c*8, c*8+8). Wh slice [1024 x 8] kept transposed in SMEM
// for the whole layer. Per step: h (transposed [k][b]) copied global->SMEM,
// warps 0-3 handle k in [0,512), warps 4-7 k in [512,1024); each thread computes
// 2 columns for its lane's batch row; SMEM reduce joins the two K halves.
// h_new is written both back into xp (in-place: xp buffer becomes next layer's
// input sequence) and into the transposed global ping-pong h buffer.
__global__ void __launch_bounds__(256, 1)
rnn_layer_kernel(float* __restrict__ xp, const float* __restrict__ Wh)
{
    extern __shared__ float sm[];
    float* Wh_s = sm;                        // [CPC][HH]  (Wh_s[c][k] = Wh[k][c0+c])
    float* h_s  = sm + CPC * HH;             // [HH][BB]   (h_s[k*32 + b])
    float* red  = sm + CPC * HH + HH * BB;   // [4][2][32] partial sums

    const int tid = threadIdx.x;
    const int cta = blockIdx.x;
    const int c0  = cta * CPC;

    // load Wh slice (transposed) once per layer
    for (int i = tid; i < CPC * HH; i += 256) {
        int c = i & (CPC - 1);
        int k = i >> 3;
        Wh_s[c * HH + k] = Wh[k * HH + c0 + c];
    }
    // zero initial hidden state (g_hA is the t=0 "current" buffer)
    g_hA[cta * 256 + tid] = 0.0f;

    unsigned bar = 1;
    grid_bar_sync(bar * NCTA); bar++;

    const int w    = tid >> 5;
    const int lane = tid & 31;              // lane == batch index
    const int khalf = (w >> 2) * 512;       // warps 0-3: k<512, warps 4-7: k>=512
    const int cp    = (w & 3) * 2;          // column pair within the CTA's 8 cols
    const int redb  = (w & 3) * 64;

    float* hcur = g_hA;
    float* hnxt = g_hB;

    for (int t = 0; t < TT; t++) {
        // prefetch xp values for the finalizing warps (hides LDG latency)
        float xv0 = 0.0f, xv1 = 0.0f;
        int xidx = 0;
        if (w >= 4) {
            xidx = (lane * TT + t) * HH + c0 + cp;
            xv0 = xp[xidx];
            xv1 = xp[xidx + 1];
        }

        // broadcast h_t into SMEM (coalesced float4 copy, 32 in flight per thread)
        {
            const float4* src = (const float4*)hcur;
            float4* dst = (float4*)h_s;
#pragma unroll
            for (int i = 0; i < 32; i++)
                dst[tid + (i << 8)] = src[tid + (i << 8)];
        }
        __syncthreads();

        // partial dot over this warp's K half, 2 columns per thread
        float acc0 = 0.0f, acc1 = 0.0f;
        const float* wr0 = Wh_s + (cp + 0) * HH + khalf;
        const float* wr1 = Wh_s + (cp + 1) * HH + khalf;
        const float* hp  = h_s + khalf * BB + lane;
#pragma unroll 8
        for (int k = 0; k < 512; k += 4) {
            float4 wa = *(const float4*)(wr0 + k);
            float4 wb = *(const float4*)(wr1 + k);
            float h0 = hp[(k + 0) * BB];
            float h1 = hp[(k + 1) * BB];
            float h2 = hp[(k + 2) * BB];
            float h3 = hp[(k + 3) * BB];
            acc0 = fmaf(h0, wa.x, acc0);
            acc1 = fmaf(h0, wb.x, acc1);
            acc0 = fmaf(h1, wa.y, acc0);
            acc1 = fmaf(h1, wb.y, acc1);
            acc0 = fmaf(h2, wa.z, acc0);
            acc1 = fmaf(h2, wb.z, acc1);
            acc0 = fmaf(h3, wa.w, acc0);
            acc1 = fmaf(h3, wb.w, acc1);
        }

        if (w < 4) {
            red[redb + lane]      = acc0;
            red[redb + 32 + lane] = acc1;
        }
        __syncthreads();

        if (w >= 4) {
            float t0 = acc0 + red[redb + lane];
            float t1 = acc1 + red[redb + 32 + lane];
            float hn0 = tanh_acc(xv0 + t0);
            float hn1 = tanh_acc(xv1 + t1);
            xp[xidx]     = hn0;                       // in-place: becomes next layer's seq
            xp[xidx + 1] = hn1;
            hnxt[(c0 + cp + 0) * BB + lane] = hn0;    // transposed h for next step
            hnxt[(c0 + cp + 1) * BB + lane] = hn1;
        }

        grid_bar_sync(bar * NCTA); bar++;
        float* tmp = hcur; hcur = hnxt; hnxt = tmp;
    }
}

// -------------------- Final dense head: out[32,1024] = h_last @ fcW + fcb ------------
__global__ void __launch_bounds__(256)
fc_kernel(const float* __restrict__ seq, const float* __restrict__ fcW,
          const float* __restrict__ fcb, float* __restrict__ out)
{
    const int o = blockIdx.x * 256 + threadIdx.x;
    const int b = blockIdx.y;
    const float* h = seq + (b * TT + (TT - 1)) * HH;
    float acc = fcb[o];
#pragma unroll 8
    for (int k = 0; k < HH; k++)
        acc = fmaf(h[k], fcW[k * HH + o], acc);
    out[b * HH + o] = acc;
}

// -------------------- launch --------------------
extern "C" void kernel_launch(void* const* d_in, const int* in_sizes, int n_in,
                              void* d_out, int out_size)
{
    const float* x   = (const float*)d_in[0];   // [32,1024,1024]
    const float* Wi  = (const float*)d_in[1];   // [4,1024,1024]
    const float* Wh  = (const float*)d_in[2];   // [4,1024,1024]
    const float* bl  = (const float*)d_in[3];   // [4,1024]
    const float* fcW = (const float*)d_in[4];   // [1024,1024]
    const float* fcb = (const float*)d_in[5];   // [1024]
    float* out = (float*)d_out;                 // [32,1024] f32

    cudaFuncSetAttribute(rnn_layer_kernel,
                         cudaFuncAttributeMaxDynamicSharedMemorySize, RNN_SMEM);

    float *S0, *S1;
    cudaGetSymbolAddress((void**)&S0, g_S0);
    cudaGetSymbolAddress((void**)&S1, g_S1);

    const dim3 ggrid(8, 256);   // N tiles x M tiles

    // layer 0: x -> S0
    gemm_bias_kernel<<<ggrid, 256>>>(x,  Wi,               bl,           S0);
    rnn_layer_kernel<<<NCTA, 256, RNN_SMEM>>>(S0, Wh);
    // layer 1: S0 -> S1
    gemm_bias_kernel<<<ggrid, 256>>>(S0, Wi + 1 * HH * HH, bl + 1 * HH,  S1);
    rnn_layer_kernel<<<NCTA, 256, RNN_SMEM>>>(S1, Wh + 1 * HH * HH);
    // layer 2: S1 -> S0
    gemm_bias_kernel<<<ggrid, 256>>>(S1, Wi + 2 * HH * HH, bl + 2 * HH,  S0);
    rnn_layer_kernel<<<NCTA, 256, RNN_SMEM>>>(S0, Wh + 2 * HH * HH);
    // layer 3: S0 -> S1
    gemm_bias_kernel<<<ggrid, 256>>>(S0, Wi + 3 * HH * HH, bl + 3 * HH,  S1);
    rnn_layer_kernel<<<NCTA, 256, RNN_SMEM>>>(S1, Wh + 3 * HH * HH);

    // head on last timestep of final layer
    fc_kernel<<<dim3(HH / 256, BB), 256>>>(S1, fcW, fcb, out);
}